// round 16
// baseline (speedup 1.0000x reference)
#include <cuda_runtime.h>
#include <math.h>
#include <stdint.h>

typedef unsigned long long u64;

#define S_SPLIT 32
#define KC      128

__device__ float g_qkv_part[S_SPLIT * 32 * 6144];
__device__ float g_qkv[32 * 6144];
__device__ float g_attn[32 * 4096];
__device__ float g_wo_part[S_SPLIT * 32 * 4096];

__device__ __forceinline__ u64 f2pack(float lo, float hi) {
    u64 r; asm("mov.b64 %0,{%1,%2};" : "=l"(r) : "f"(lo), "f"(hi)); return r;
}
__device__ __forceinline__ u64 ffma2(u64 a, u64 b, u64 c) {
    u64 d; asm("fma.rn.f32x2 %0,%1,%2,%3;" : "=l"(d) : "l"(a), "l"(b), "l"(c)); return d;
}
__device__ __forceinline__ u64 fmul2(u64 a, u64 b) {
    u64 d; asm("mul.rn.f32x2 %0,%1,%2;" : "=l"(d) : "l"(a), "l"(b)); return d;
}
__device__ __forceinline__ float f2lo(u64 v) {
    float lo, hi; asm("mov.b64 {%0,%1},%2;" : "=f"(lo), "=f"(hi) : "l"(v)); return lo;
}
__device__ __forceinline__ float f2hi(u64 v) {
    float lo, hi; asm("mov.b64 {%0,%1},%2;" : "=f"(lo), "=f"(hi) : "l"(v)); return hi;
}
__device__ __forceinline__ uint32_t s2u(const void* p) {
    return (uint32_t)__cvta_generic_to_shared(p);
}
__device__ __forceinline__ void cp16(uint32_t dst, const void* src) {
    asm volatile("cp.async.cg.shared.global [%0], [%1], 16;" :: "r"(dst), "l"(src));
}
#define CP_COMMIT() asm volatile("cp.async.commit_group;")
#define CP_WAIT(n)  asm volatile("cp.async.wait_group %0;" :: "n"(n))

// ---- split-K GEMM partial with cp.async W staging -------------------------
#define GNST 4
__global__ __launch_bounds__(128, 2)
void gemm_split(const float* __restrict__ A, const float* __restrict__ W,
                float* __restrict__ part, int N)
{
    __shared__ float2 as2[32][KC];          // 32768 B
    __shared__ float  wstg[GNST][1024];     // 16384 B
    const int K = 4096;
    const int k0 = blockIdx.y * KC;
    const int tid = threadIdx.x;

    for (int i = tid; i < 32 * KC; i += 128) {
        int m = i >> 7, kk = i & (KC - 1);
        float a = A[m * K + k0 + kk];
        as2[m][kk] = make_float2(a, a);
    }

    const uint32_t wbase = s2u(wstg);
    const float* Wrow = W + (size_t)k0 * N + blockIdx.x * 512 + tid * 4;
#pragma unroll
    for (int s = 0; s < GNST - 1; s++) {
        cp16(wbase + (uint32_t)((s * 1024 +   0) + tid * 4) * 4u,
             Wrow + (size_t)(2 * s) * N);
        cp16(wbase + (uint32_t)((s * 1024 + 512) + tid * 4) * 4u,
             Wrow + (size_t)(2 * s + 1) * N);
        CP_COMMIT();
    }
    __syncthreads();

    u64 acc01[32], acc23[32];
#pragma unroll
    for (int m = 0; m < 32; m++) { acc01[m] = 0ull; acc23[m] = 0ull; }

#pragma unroll 1
    for (int it = 0; it < 64; it++) {
        CP_WAIT(2);
        const float* ws = wstg[it & (GNST - 1)];
        u64 wa0 = *(const u64*)(ws + tid * 4);
        u64 wa1 = *(const u64*)(ws + tid * 4 + 2);
        u64 wb0 = *(const u64*)(ws + 512 + tid * 4);
        u64 wb1 = *(const u64*)(ws + 512 + tid * 4 + 2);
        if (it + GNST - 1 < 64) {
            int s = (it + GNST - 1) & (GNST - 1);
            cp16(wbase + (uint32_t)((s * 1024 +   0) + tid * 4) * 4u,
                 Wrow + (size_t)(2 * (it + GNST - 1)) * N);
            cp16(wbase + (uint32_t)((s * 1024 + 512) + tid * 4) * 4u,
                 Wrow + (size_t)(2 * (it + GNST - 1) + 1) * N);
            CP_COMMIT();
        } else {
            CP_COMMIT();
        }
        const int kk = 2 * it;
#pragma unroll
        for (int m = 0; m < 32; m++) {
            const u64* pa = (const u64*)&as2[m][kk];
            u64 a0 = pa[0], a1 = pa[1];
            acc01[m] = ffma2(a0, wa0, acc01[m]);
            acc23[m] = ffma2(a0, wa1, acc23[m]);
            acc01[m] = ffma2(a1, wb0, acc01[m]);
            acc23[m] = ffma2(a1, wb1, acc23[m]);
        }
    }

    float* op = part + (size_t)blockIdx.y * 32 * N + blockIdx.x * 512 + tid * 4;
#pragma unroll
    for (int m = 0; m < 32; m++) {
        *(u64*)(op + (size_t)m * N)     = acc01[m];
        *(u64*)(op + (size_t)m * N + 2) = acc23[m];
    }
}

// ---- reduce QKV partials + RoPE; grid (32 rows, 4 col-chunks) -------------
__global__ void qkv_reduce_rope(const int* __restrict__ pos1d)
{
    __shared__ float cs[64], sn[64];
    const int b = blockIdx.x;
    const int tid = threadIdx.x;

    if (tid < 64) {
        float freq = (float)pow(1.0e6, -(double)tid / 64.0);
        float ang = (float)pos1d[b] * freq;
        double sd, cd; sincos((double)ang, &sd, &cd);
        cs[tid] = (float)cd; sn[tid] = (float)sd;
    }
    __syncthreads();

    const int beg = blockIdx.y * 896, end = beg + 896;
    for (int idx = beg + tid; idx < end; idx += 256) {
        if (idx < 2560) {
            int col1, j;
            if (idx < 2048) { int h = idx >> 6; j = idx & 63; col1 = h * 128 + j; }
            else { int t = idx - 2048; int kvh = t >> 6; j = t & 63; col1 = 4096 + kvh * 128 + j; }
            int col2 = col1 + 64;
            float x1 = 0.f, x2 = 0.f;
#pragma unroll
            for (int s = 0; s < S_SPLIT; s++) {
                x1 += g_qkv_part[(s * 32 + b) * 6144 + col1];
                x2 += g_qkv_part[(s * 32 + b) * 6144 + col2];
            }
            float c = cs[j], sv = sn[j];
            g_qkv[b * 6144 + col1] = x1 * c - x2 * sv;
            g_qkv[b * 6144 + col2] = x2 * c + x1 * sv;
        } else {
            int col = 5120 + (idx - 2560);
            float x = 0.f;
#pragma unroll
            for (int s = 0; s < S_SPLIT; s++)
                x += g_qkv_part[(s * 32 + b) * 6144 + col];
            g_qkv[b * 6144 + col] = x;
        }
    }
}

// ---- flash-decode paged GQA attention, per-warp cp.async pipelines --------
#define W_STEPS  128
#define ROW_F    132
#define STG_FL   (8 * ROW_F)
#define WNSTAGE  3
#define WARP_STG (WNSTAGE * STG_FL)
#define ATTN_SMEM ((8 * WARP_STG + 512 + 104) * 4)

__global__ __launch_bounds__(256, 2)
void attn_kernel(const float* __restrict__ kc, const float* __restrict__ vc,
                 const int* __restrict__ blkoff, const int* __restrict__ kvlens)
{
    extern __shared__ float sm[];
    float* stg  = sm;
    float* qp   = sm + 8 * WARP_STG;
    float* msm  = qp + 512;
    float* ssm  = msm + 32;
    float* wgt  = ssm + 32;
    float* invS = wgt + 32;
    __shared__ int pblk[64];

    const int b = blockIdx.x >> 3, kvh = blockIdx.x & 7;
    const int tid = threadIdx.x;
    const int Lv = kvlens[b];
    const int posn = Lv - 1;
    const float* qkv_b = g_qkv + b * 6144;

    for (int i = tid; i < 512; i += 256) {
        int g = i >> 7, d = i & 127;
        qp[i] = qkv_b[(kvh * 4 + g) * 128 + d] * 0.08838834764831845f;
    }
    if (tid < 64) pblk[tid] = blkoff[b * 64 + tid];
    __syncthreads();

    const int wv = tid >> 5, ln = tid & 31;
    const int lane16 = ln & 15, half = ln >> 4;
    const int rbase = wv * 512;
    float* wstg = stg + wv * WARP_STG;
    const uint32_t wstg_u32 = s2u(wstg);
    const float* kfresh = qkv_b + 4096 + kvh * 128;
    const float* vfresh = qkv_b + 5120 + kvh * 128;

    // q packed over dim-pairs: qq[g][0..1] dims lane16*4..+3, [2..3] dims 64+lane16*4..+3
    u64 qq[4][4];
#pragma unroll
    for (int g = 0; g < 4; g++) {
        const u64* qa = (const u64*)&qp[g * 128 + lane16 * 4];
        const u64* qb = (const u64*)&qp[g * 128 + 64 + lane16 * 4];
        qq[g][0] = qa[0]; qq[g][1] = qa[1];
        qq[g][2] = qb[0]; qq[g][3] = qb[1];
    }

    // Step loader: one block lookup; rows of a step share the cache block.
#define LOAD_STEP(st, slot)                                                     \
    do {                                                                        \
        uint32_t sb = wstg_u32 + (uint32_t)((slot) * STG_FL) * 4u                \
                      + (uint32_t)(ln * 4) * 4u;                                \
        int l0 = rbase + (st) * 4;                                              \
        int phys = pblk[l0 >> 6];                                               \
        size_t boff = (((size_t)phys * 64 + (l0 & 63)) * 8 + kvh) * 128 + ln*4; \
        const float* ks = kc + boff;                                            \
        const float* vs = vc + boff;                                            \
        _Pragma("unroll")                                                       \
        for (int j = 0; j < 4; j++) {                                           \
            const float* sk = (l0 + j == posn) ? kfresh + ln * 4 : ks + j*1024; \
            cp16(sb + (uint32_t)(j * ROW_F) * 4u, sk);                          \
        }                                                                       \
        _Pragma("unroll")                                                       \
        for (int j = 0; j < 4; j++) {                                           \
            const float* sv = (l0 + j == posn) ? vfresh + ln * 4 : vs + j*1024; \
            cp16(sb + (uint32_t)((4 + j) * ROW_F) * 4u, sv);                    \
        }                                                                       \
        CP_COMMIT();                                                            \
    } while (0)

    LOAD_STEP(0, 0);
    LOAD_STEP(1, 1);

    float4 m = make_float4(-1e30f, -1e30f, -1e30f, -1e30f);
    float4 s = make_float4(0.f, 0.f, 0.f, 0.f);
    u64 od[4][2];                              // o[g], packed over this lane's dim pairs
#pragma unroll
    for (int g = 0; g < 4; g++) { od[g][0] = 0ull; od[g][1] = 0ull; }

#pragma unroll 1
    for (int t = 0; t < W_STEPS; t++) {
        __syncwarp();
        if (t + 2 < W_STEPS) LOAD_STEP(t + 2, (t + 2) % WNSTAGE);
        else CP_COMMIT();
        CP_WAIT(2);
        __syncwarp();
        const float* kb = wstg + (t % WNSTAGE) * STG_FL;
        const float* vb = kb + 4 * ROW_F;

        // ---- QK: packed f32x2 dot; this thread handles rows (pass*2+half)
        float4 sA, sB;
#pragma unroll
        for (int pass = 0; pass < 2; pass++) {
            int r = pass * 2 + half;
            ulonglong2 kA = *(const ulonglong2*)(kb + r * ROW_F + lane16 * 4);
            ulonglong2 kB = *(const ulonglong2*)(kb + r * ROW_F + 64 + lane16 * 4);
            float a0, a1, a2, a3;
            {
                u64 c0 = fmul2(kA.x, qq[0][0]);
                c0 = ffma2(kA.y, qq[0][1], c0);
                c0 = ffma2(kB.x, qq[0][2], c0);
                c0 = ffma2(kB.y, qq[0][3], c0);
                a0 = f2lo(c0) + f2hi(c0);
                u64 c1 = fmul2(kA.x, qq[1][0]);
                c1 = ffma2(kA.y, qq[1][1], c1);
                c1 = ffma2(kB.x, qq[1][2], c1);
                c1 = ffma2(kB.y, qq[1][3], c1);
                a1 = f2lo(c1) + f2hi(c1);
                u64 c2 = fmul2(kA.x, qq[2][0]);
                c2 = ffma2(kA.y, qq[2][1], c2);
                c2 = ffma2(kB.x, qq[2][2], c2);
                c2 = ffma2(kB.y, qq[2][3], c2);
                a2 = f2lo(c2) + f2hi(c2);
                u64 c3 = fmul2(kA.x, qq[3][0]);
                c3 = ffma2(kA.y, qq[3][1], c3);
                c3 = ffma2(kB.x, qq[3][2], c3);
                c3 = ffma2(kB.y, qq[3][3], c3);
                a3 = f2lo(c3) + f2hi(c3);
            }
#pragma unroll
            for (int o = 8; o > 0; o >>= 1) {
                a0 += __shfl_xor_sync(0xffffffffu, a0, o);
                a1 += __shfl_xor_sync(0xffffffffu, a1, o);
                a2 += __shfl_xor_sync(0xffffffffu, a2, o);
                a3 += __shfl_xor_sync(0xffffffffu, a3, o);
            }
            if (rbase + t * 4 + r >= Lv) { a0 = a1 = a2 = a3 = -1e30f; }
            if (pass == 0) sA = make_float4(a0, a1, a2, a3);
            else           sB = make_float4(a0, a1, a2, a3);
        }
        float4 tA, tB;
        tA.x = __shfl_xor_sync(0xffffffffu, sA.x, 16);
        tA.y = __shfl_xor_sync(0xffffffffu, sA.y, 16);
        tA.z = __shfl_xor_sync(0xffffffffu, sA.z, 16);
        tA.w = __shfl_xor_sync(0xffffffffu, sA.w, 16);
        tB.x = __shfl_xor_sync(0xffffffffu, sB.x, 16);
        tB.y = __shfl_xor_sync(0xffffffffu, sB.y, 16);
        tB.z = __shfl_xor_sync(0xffffffffu, sB.z, 16);
        tB.w = __shfl_xor_sync(0xffffffffu, sB.w, 16);
        float4 r0 = half ? tA : sA;
        float4 r1 = half ? sA : tA;
        float4 r2 = half ? tB : sB;
        float4 r3 = half ? sB : tB;

        // ---- online softmax -------------------------------------------
        float4 mn;
        mn.x = fmaxf(fmaxf(fmaxf(r0.x, r1.x), fmaxf(r2.x, r3.x)), m.x);
        mn.y = fmaxf(fmaxf(fmaxf(r0.y, r1.y), fmaxf(r2.y, r3.y)), m.y);
        mn.z = fmaxf(fmaxf(fmaxf(r0.z, r1.z), fmaxf(r2.z, r3.z)), m.z);
        mn.w = fmaxf(fmaxf(fmaxf(r0.w, r1.w), fmaxf(r2.w, r3.w)), m.w);
        float4 p0, p1, p2, p3;
        p0.x = __expf(r0.x - mn.x); p0.y = __expf(r0.y - mn.y);
        p0.z = __expf(r0.z - mn.z); p0.w = __expf(r0.w - mn.w);
        p1.x = __expf(r1.x - mn.x); p1.y = __expf(r1.y - mn.y);
        p1.z = __expf(r1.z - mn.z); p1.w = __expf(r1.w - mn.w);
        p2.x = __expf(r2.x - mn.x); p2.y = __expf(r2.y - mn.y);
        p2.z = __expf(r2.z - mn.z); p2.w = __expf(r2.w - mn.w);
        p3.x = __expf(r3.x - mn.x); p3.y = __expf(r3.y - mn.y);
        p3.z = __expf(r3.z - mn.z); p3.w = __expf(r3.w - mn.w);
        float4 ps;
        ps.x = p0.x + p1.x + p2.x + p3.x;
        ps.y = p0.y + p1.y + p2.y + p3.y;
        ps.z = p0.z + p1.z + p2.z + p3.z;
        ps.w = p0.w + p1.w + p2.w + p3.w;
        // warp-uniform: rescale only when max actually moved (exp(0)==1 exact)
        if (mn.x != m.x || mn.y != m.y || mn.z != m.z || mn.w != m.w) {
            float4 sc4;
            sc4.x = __expf(m.x - mn.x); sc4.y = __expf(m.y - mn.y);
            sc4.z = __expf(m.z - mn.z); sc4.w = __expf(m.w - mn.w);
            s.x = s.x * sc4.x; s.y = s.y * sc4.y;
            s.z = s.z * sc4.z; s.w = s.w * sc4.w;
            u64 sg0 = f2pack(sc4.x, sc4.x), sg1 = f2pack(sc4.y, sc4.y);
            u64 sg2 = f2pack(sc4.z, sc4.z), sg3 = f2pack(sc4.w, sc4.w);
            od[0][0] = fmul2(od[0][0], sg0); od[0][1] = fmul2(od[0][1], sg0);
            od[1][0] = fmul2(od[1][0], sg1); od[1][1] = fmul2(od[1][1], sg1);
            od[2][0] = fmul2(od[2][0], sg2); od[2][1] = fmul2(od[2][1], sg2);
            od[3][0] = fmul2(od[3][0], sg3); od[3][1] = fmul2(od[3][1], sg3);
            m = mn;
        }
        s.x += ps.x; s.y += ps.y; s.z += ps.z; s.w += ps.w;

        // ---- PV: V as u64 pairs, p duplicated per head ---------------------
#define PVROW(r, pp)                                                       \
        do {                                                               \
            ulonglong2 vv = *(const ulonglong2*)(vb + (r) * ROW_F + ln*4); \
            u64 pg0 = f2pack(pp.x, pp.x), pg1 = f2pack(pp.y, pp.y);        \
            u64 pg2 = f2pack(pp.z, pp.z), pg3 = f2pack(pp.w, pp.w);        \
            od[0][0] = ffma2(vv.x, pg0, od[0][0]);                         \
            od[0][1] = ffma2(vv.y, pg0, od[0][1]);                         \
            od[1][0] = ffma2(vv.x, pg1, od[1][0]);                         \
            od[1][1] = ffma2(vv.y, pg1, od[1][1]);                         \
            od[2][0] = ffma2(vv.x, pg2, od[2][0]);                         \
            od[2][1] = ffma2(vv.y, pg2, od[2][1]);                         \
            od[3][0] = ffma2(vv.x, pg3, od[3][0]);                         \
            od[3][1] = ffma2(vv.y, pg3, od[3][1]);                         \
        } while (0)
        PVROW(0, p0); PVROW(1, p1); PVROW(2, p2); PVROW(3, p3);
#undef PVROW
    }
    CP_WAIT(0);

    // ---- merge 8 warps' (m, s, o) ----------------------------------------
    __syncthreads();
    if (ln == 0) {
        msm[wv * 4 + 0] = m.x; msm[wv * 4 + 1] = m.y;
        msm[wv * 4 + 2] = m.z; msm[wv * 4 + 3] = m.w;
        ssm[wv * 4 + 0] = s.x; ssm[wv * 4 + 1] = s.y;
        ssm[wv * 4 + 2] = s.z; ssm[wv * 4 + 3] = s.w;
    }
    float* ov = stg;                           // reuse staging: [(w*32+ln)*16 + g*4 + c]
#pragma unroll
    for (int g = 0; g < 4; g++)
        ((float4*)(ov + (wv * 32 + ln) * 16))[g] =
            make_float4(f2lo(od[g][0]), f2hi(od[g][0]),
                        f2lo(od[g][1]), f2hi(od[g][1]));
    __syncthreads();
    if (tid < 4) {
        int g = tid;
        float M = -1e30f;
#pragma unroll
        for (int w = 0; w < 8; w++) M = fmaxf(M, msm[w * 4 + g]);
        float S = 0.f;
#pragma unroll
        for (int w = 0; w < 8; w++) {
            float e = __expf(msm[w * 4 + g] - M);
            wgt[w * 4 + g] = e;
            S += ssm[w * 4 + g] * e;
        }
        invS[g] = 1.f / S;
    }
    __syncthreads();
    if (tid < 128) {
        int dl = tid >> 2, g = tid & 3;        // lane dl's 4 dims, head g
        float4 o = make_float4(0.f, 0.f, 0.f, 0.f);
#pragma unroll
        for (int w = 0; w < 8; w++) {
            float4 pw = ((const float4*)(ov + (w * 32 + dl) * 16))[g];
            float e = wgt[w * 4 + g];
            o.x += pw.x * e; o.y += pw.y * e; o.z += pw.z * e; o.w += pw.w * e;
        }
        float is = invS[g];
        float* ob = g_attn + b * 4096 + kvh * 512 + g * 128 + dl * 4;
        ob[0] = o.x * is; ob[1] = o.y * is; ob[2] = o.z * is; ob[3] = o.w * is;
    }
}

// ---- final split-K reduction ----------------------------------------------
__global__ void reduce_out(float* __restrict__ out, int n)
{
    int i = blockIdx.x * blockDim.x + threadIdx.x;
    if (i < n) {
        float x = 0.f;
#pragma unroll
        for (int s = 0; s < S_SPLIT; s++) x += g_wo_part[(size_t)s * n + i];
        out[i] = x;
    }
}

extern "C" void kernel_launch(void* const* d_in, const int* in_sizes, int n_in,
                              void* d_out, int out_size)
{
    const float* hidden = (const float*)d_in[0];
    const float* wqkv   = (const float*)d_in[1];
    const float* wo     = (const float*)d_in[2];
    const float* kc     = (const float*)d_in[3];
    const float* vc     = (const float*)d_in[4];
    const int*   pos1d  = (const int*)d_in[5];
    const int*   blkoff = (const int*)d_in[6];
    const int*   kvlens = (const int*)d_in[7];
    float* out = (float*)d_out;

    static bool attr_done = false;
    if (!attr_done) {
        cudaFuncSetAttribute(attn_kernel, cudaFuncAttributeMaxDynamicSharedMemorySize, ATTN_SMEM);
        attr_done = true;
    }

    float *qkv_part, *wo_part, *attn_in;
    cudaGetSymbolAddress((void**)&qkv_part, g_qkv_part);
    cudaGetSymbolAddress((void**)&wo_part,  g_wo_part);
    cudaGetSymbolAddress((void**)&attn_in,  g_attn);

    // 2 harness pre-launches + these: WO gemm lands at global #6 (ncu -s 5)
    gemm_split<<<dim3(12, 32), 128>>>(hidden, wqkv, qkv_part, 6144);
    qkv_reduce_rope<<<dim3(32, 4), 256>>>(pos1d);
    attn_kernel<<<256, 256, ATTN_SMEM>>>(kc, vc, blkoff, kvlens);
    gemm_split<<<dim3(8, 32), 128>>>(attn_in, wo, wo_part, 4096);
    reduce_out<<<512, 256>>>(out, 32 * 4096);
}